// round 6
// baseline (speedup 1.0000x reference)
#include <cuda_runtime.h>
#include <cuda_bf16.h>
#include <cstdint>

// Closed-form per-(batch,class) reduction of the symmetric-pair loss.
// For a group of n points of one symmetric class (c in {0,1,2}), with
// u_i = x_i - CENTER_X:
//   sum_{i<j} (u_i+u_j)^2 = (n-2)*Sum(u^2) + (Sum u)^2
//   sum_{i<j} (y_i-y_j)^2 =  n   *Sum(y^2) - (Sum y)^2
//   #pairs                =  n(n-1)/2
// Both identities are exactly 0 for n in {0,1}.
//
// kernel1: ONE WARP per batch (256 CTAs x 32 threads) — no smem, no
//          __syncthreads, all-float math, REDUX for integer counts.
// finalize: PDL-overlapped single warp; double only for the final
//          256-element accumulation.

#define CENTER_X 0.5f
#define BATCH 256
#define NPTS  512

__device__ float2 g_partial[BATCH];  // (loss, count) per batch

__global__ void __launch_bounds__(32) sym_per_batch(const float* __restrict__ kp,
                                                    const int* __restrict__ cls) {
    const int b = blockIdx.x;
    const int l = threadIdx.x;

    const float4* kp4 = reinterpret_cast<const float4*>(kp) + (size_t)b * (NPTS / 2);
    const int4*   c4p = reinterpret_cast<const int4*>(cls) + (size_t)b * (NPTS / 4);

    float su[3], su2[3], sy[3], sy2[3];
    int   cn[3];
#pragma unroll
    for (int k = 0; k < 3; k++) { su[k] = su2[k] = sy[k] = sy2[k] = 0.0f; cn[k] = 0; }

#pragma unroll
    for (int s = 0; s < 4; s++) {
        const int g = l + 32 * s;            // point-group of 4
        const int4   c4 = c4p[g];
        const float4 a  = kp4[2 * g];        // points 4g, 4g+1
        const float4 q  = kp4[2 * g + 1];    // points 4g+2, 4g+3

        const float px[4] = {a.x, a.z, q.x, q.z};
        const float py[4] = {a.y, a.w, q.y, q.w};
        const int   pc[4] = {c4.x, c4.y, c4.z, c4.w};
#pragma unroll
        for (int j = 0; j < 4; j++) {
            const float u = px[j] - CENTER_X;
            const float y = py[j];
#pragma unroll
            for (int k = 0; k < 3; k++) {
                if (pc[j] == k) {
                    su[k]  += u;
                    su2[k]  = fmaf(u, u, su2[k]);
                    sy[k]  += y;
                    sy2[k]  = fmaf(y, y, sy2[k]);
                    cn[k]  += 1;
                }
            }
        }
    }

    // Intra-warp reduction: 12 float accumulators via shuffles,
    // 3 int counts via single-instruction REDUX.
#pragma unroll
    for (int off = 16; off > 0; off >>= 1) {
#pragma unroll
        for (int k = 0; k < 3; k++) {
            su[k]  += __shfl_down_sync(0xffffffffu, su[k],  off);
            su2[k] += __shfl_down_sync(0xffffffffu, su2[k], off);
            sy[k]  += __shfl_down_sync(0xffffffffu, sy[k],  off);
            sy2[k] += __shfl_down_sync(0xffffffffu, sy2[k], off);
        }
    }
    int cnt[3];
#pragma unroll
    for (int k = 0; k < 3; k++)
        cnt[k] = __reduce_add_sync(0xffffffffu, cn[k]);

    if (l == 0) {
        float loss = 0.0f, count = 0.0f;
#pragma unroll
        for (int k = 0; k < 3; k++) {
            const float n = (float)cnt[k];
            loss  += (n - 2.0f) * su2[k] + su[k] * su[k] + n * sy2[k] - sy[k] * sy[k];
            count += n * (n - 1.0f) * 0.5f;
        }
        g_partial[b] = make_float2(loss, count);
    }

#if __CUDA_ARCH__ >= 900
    cudaTriggerProgrammaticLaunchCompletion();
#endif
}

__global__ void __launch_bounds__(32) sym_finalize(float* __restrict__ out) {
#if __CUDA_ARCH__ >= 900
    cudaGridDependencySynchronize();  // full visibility of g_partial
#endif
    const int l = threadIdx.x;
    // 256 float2 partials = 128 float4; each lane reads 4 coalesced float4.
    const float4* p4 = reinterpret_cast<const float4*>(g_partial);
    double L = 0.0, C = 0.0;
#pragma unroll
    for (int i = 0; i < 4; i++) {
        const float4 v = p4[l + 32 * i];
        L += (double)v.x + (double)v.z;
        C += (double)v.y + (double)v.w;
    }
#pragma unroll
    for (int off = 16; off > 0; off >>= 1) {
        L += __shfl_down_sync(0xffffffffu, L, off);
        C += __shfl_down_sync(0xffffffffu, C, off);
    }
    if (l == 0) {
        const double c = C < 1.0 ? 1.0 : C;
        out[0] = (float)(L / c);
    }
}

extern "C" void kernel_launch(void* const* d_in, const int* in_sizes, int n_in,
                              void* d_out, int out_size) {
    const float* kp  = (const float*)d_in[0];  // [256, 512, 2] f32
    const int*   cls = (const int*)d_in[1];    // [256, 512] i32
    float* out = (float*)d_out;

    sym_per_batch<<<BATCH, 32>>>(kp, cls);

    // Finalize with Programmatic Dependent Launch to overlap launch latency.
    cudaLaunchConfig_t cfg = {};
    cfg.gridDim  = dim3(1, 1, 1);
    cfg.blockDim = dim3(32, 1, 1);
    cfg.dynamicSmemBytes = 0;
    cfg.stream = 0;
    cudaLaunchAttribute attr[1];
    attr[0].id = cudaLaunchAttributeProgrammaticStreamSerialization;
    attr[0].val.programmaticStreamSerializationAllowed = 1;
    cfg.attrs = attr;
    cfg.numAttrs = 1;

    cudaError_t e = cudaLaunchKernelEx(&cfg, sym_finalize, out);
    if (e != cudaSuccess) {
        sym_finalize<<<1, 32>>>(out);
    }
}

// round 7
// speedup vs baseline: 1.0304x; 1.0304x over previous
#include <cuda_runtime.h>
#include <cuda_bf16.h>
#include <cstdint>

// Closed-form per-(batch,class) reduction of the symmetric-pair loss.
// For a group of n points of one symmetric class (c in {0,1,2}), with
// u_i = x_i - CENTER_X:
//   sum_{i<j} (u_i+u_j)^2 = (n-2)*Sum(u^2) + (Sum u)^2
//   sum_{i<j} (y_i-y_j)^2 =  n   *Sum(y^2) - (Sum y)^2
//   #pairs                =  n(n-1)/2
// Both identities are exactly 0 for n in {0,1}.
//
// kernel1: 64 CTAs x 1024 threads; each CTA handles 4 batches (8 warps /
//          batch, 2 points / thread — the R5-proven shape), REDUX int
//          counts, warp-parallel cross-warp combine. All-float math.
// finalize: PDL-overlapped single warp; double only for the final
//          256-element accumulation.

#define CENTER_X 0.5f
#define BATCH 256
#define NPTS  512

__device__ float2 g_partial[BATCH];  // (loss, count) per batch

__global__ void __launch_bounds__(1024) sym_per_batch(const float* __restrict__ kp,
                                                      const int* __restrict__ cls) {
    const int t = threadIdx.x;
    const int w   = t >> 5;        // warp 0..31
    const int lid = t & 31;
    const int grp = w >> 3;        // batch-group within CTA: 0..3
    const int wi  = w & 7;         // warp within group: 0..7

    const int b  = blockIdx.x * 4 + grp;      // batch handled by this group
    const int tg = wi * 32 + lid;             // thread index within group: 0..255

    // Each thread handles 2 consecutive points: 1x float4 + 1x int2.
    const float4 p = reinterpret_cast<const float4*>(kp)[(size_t)b * 256 + tg];
    const int2   c = reinterpret_cast<const int2*>(cls)[(size_t)b * 256 + tg];

    float su[3], su2[3], sy[3], sy2[3];
    int   cn[3];
#pragma unroll
    for (int k = 0; k < 3; k++) { su[k] = su2[k] = sy[k] = sy2[k] = 0.0f; cn[k] = 0; }

    const float ux[2] = {p.x - CENTER_X, p.z - CENTER_X};
    const float yy[2] = {p.y, p.w};
    const int   cc[2] = {c.x, c.y};
#pragma unroll
    for (int j = 0; j < 2; j++) {
#pragma unroll
        for (int k = 0; k < 3; k++) {
            if (cc[j] == k) {
                su[k]  += ux[j];
                su2[k]  = fmaf(ux[j], ux[j], su2[k]);
                sy[k]  += yy[j];
                sy2[k]  = fmaf(yy[j], yy[j], sy2[k]);
                cn[k]  += 1;
            }
        }
    }

    // Intra-warp reduction: 12 float accumulators via shuffles,
    // 3 int counts via single-instruction REDUX.
#pragma unroll
    for (int off = 16; off > 0; off >>= 1) {
#pragma unroll
        for (int k = 0; k < 3; k++) {
            su[k]  += __shfl_down_sync(0xffffffffu, su[k],  off);
            su2[k] += __shfl_down_sync(0xffffffffu, su2[k], off);
            sy[k]  += __shfl_down_sync(0xffffffffu, sy[k],  off);
            sy2[k] += __shfl_down_sync(0xffffffffu, sy2[k], off);
        }
    }
    int cnt[3];
#pragma unroll
    for (int k = 0; k < 3; k++)
        cnt[k] = __reduce_add_sync(0xffffffffu, cn[k]);

    // Publish per-warp partials: 12 floats + 3 counts (as float).
    __shared__ float sf[32][16];   // padded row
    __shared__ float stot[4][16];
    if (lid == 0) {
#pragma unroll
        for (int k = 0; k < 3; k++) {
            sf[w][k * 4 + 0] = su[k];
            sf[w][k * 4 + 1] = su2[k];
            sf[w][k * 4 + 2] = sy[k];
            sf[w][k * 4 + 3] = sy2[k];
            sf[w][12 + k]    = (float)cnt[k];
        }
    }
    __syncthreads();

    // Warps 0..3: warp g combines group g's 8 warp-partials in parallel
    // (lanes 0..14 each own one accumulator), lane 0 evaluates the
    // closed form and writes the batch partial.
    if (w < 4) {
        if (lid < 15) {
            float s = 0.0f;
#pragma unroll
            for (int j = 0; j < 8; j++) s += sf[w * 8 + j][lid];
            stot[w][lid] = s;
        }
        __syncwarp();
        if (lid == 0) {
            float loss = 0.0f, count = 0.0f;
#pragma unroll
            for (int k = 0; k < 3; k++) {
                const float SU  = stot[w][k * 4 + 0];
                const float SU2 = stot[w][k * 4 + 1];
                const float SY  = stot[w][k * 4 + 2];
                const float SY2 = stot[w][k * 4 + 3];
                const float n   = stot[w][12 + k];
                loss  += (n - 2.0f) * SU2 + SU * SU + n * SY2 - SY * SY;
                count += n * (n - 1.0f) * 0.5f;
            }
            g_partial[blockIdx.x * 4 + w] = make_float2(loss, count);
        }
    }

#if __CUDA_ARCH__ >= 900
    cudaTriggerProgrammaticLaunchCompletion();
#endif
}

__global__ void __launch_bounds__(32) sym_finalize(float* __restrict__ out) {
#if __CUDA_ARCH__ >= 900
    cudaGridDependencySynchronize();  // full visibility of g_partial
#endif
    const int l = threadIdx.x;
    // 256 float2 partials = 128 float4; each lane reads 4 coalesced float4.
    const float4* p4 = reinterpret_cast<const float4*>(g_partial);
    double L = 0.0, C = 0.0;
#pragma unroll
    for (int i = 0; i < 4; i++) {
        const float4 v = p4[l + 32 * i];
        L += (double)v.x + (double)v.z;
        C += (double)v.y + (double)v.w;
    }
#pragma unroll
    for (int off = 16; off > 0; off >>= 1) {
        L += __shfl_down_sync(0xffffffffu, L, off);
        C += __shfl_down_sync(0xffffffffu, C, off);
    }
    if (l == 0) {
        const double c = C < 1.0 ? 1.0 : C;
        out[0] = (float)(L / c);
    }
}

extern "C" void kernel_launch(void* const* d_in, const int* in_sizes, int n_in,
                              void* d_out, int out_size) {
    const float* kp  = (const float*)d_in[0];  // [256, 512, 2] f32
    const int*   cls = (const int*)d_in[1];    // [256, 512] i32
    float* out = (float*)d_out;

    sym_per_batch<<<64, 1024>>>(kp, cls);

    // Finalize with Programmatic Dependent Launch to overlap launch latency.
    cudaLaunchConfig_t cfg = {};
    cfg.gridDim  = dim3(1, 1, 1);
    cfg.blockDim = dim3(32, 1, 1);
    cfg.dynamicSmemBytes = 0;
    cfg.stream = 0;
    cudaLaunchAttribute attr[1];
    attr[0].id = cudaLaunchAttributeProgrammaticStreamSerialization;
    attr[0].val.programmaticStreamSerializationAllowed = 1;
    cfg.attrs = attr;
    cfg.numAttrs = 1;

    cudaError_t e = cudaLaunchKernelEx(&cfg, sym_finalize, out);
    if (e != cudaSuccess) {
        sym_finalize<<<1, 32>>>(out);
    }
}